// round 4
// baseline (speedup 1.0000x reference)
#include <cuda_runtime.h>
#include <cstdint>

// Haar DWT2D, fused single pass, 2x4-tile, occupancy-tuned (6 CTAs/SM).
// Input:  x  (16, 1, 2048, 2048) fp32
// Output: [ll | lh | hl | hh], each (16,1,1024,1024) fp32, concatenated.
//
// Each thread: 2x4 output tile = 4 input rows x 8 cols.
//   8x LDG.128 front-batched from ONE base address (imm offsets), MLP=8.
//   8x STG.128 (two rows x four subbands) via 4 precomputed plane bases.
// __launch_bounds__(256,6) caps regs at 42 -> 6 CTAs/SM (75% occ cap).

#define B_  16
#define H_  2048
#define W_  2048
#define HO  (H_/2)            // 1024
#define WO  (W_/2)            // 1024
#define QUADS_PER_ROW (WO/4)  // 256
#define ROWPAIRS (HO/2)       // 512
#define PLANE (16u * 1024u * 1024u)  // elems per subband = 16M

__device__ __forceinline__ float safef(float v) {
    return isfinite(v) ? v : 0.0f;
}

// top=(a0,b0,a1,b1), bot=(c0,d0,c1,d1): two adjacent 2x2 blocks.
// returns float2 {block0, block1} for subband s.
__device__ __forceinline__ float2 haar2(float4 top, float4 bot, int s) {
    float a0 = safef(top.x), b0 = safef(top.y), a1 = safef(top.z), b1 = safef(top.w);
    float c0 = safef(bot.x), d0 = safef(bot.y), c1 = safef(bot.z), d1 = safef(bot.w);
    // p=a+c, q=b+d, r=c-a, t=d-b  ->  ll=.5(p+q), lh=.5(q-p), hl=.5(r+t), hh=.5(t-r)
    float p0 = a0 + c0, q0 = b0 + d0, r0 = c0 - a0, t0 = d0 - b0;
    float p1 = a1 + c1, q1 = b1 + d1, r1 = c1 - a1, t1 = d1 - b1;
    float2 v;
    switch (s) {
        case 0:  v.x = 0.5f * (p0 + q0); v.y = 0.5f * (p1 + q1); break;
        case 1:  v.x = 0.5f * (q0 - p0); v.y = 0.5f * (q1 - p1); break;
        case 2:  v.x = 0.5f * (r0 + t0); v.y = 0.5f * (r1 + t1); break;
        default: v.x = 0.5f * (t0 - r0); v.y = 0.5f * (t1 - r1); break;
    }
    return v;
}

__global__ __launch_bounds__(256, 6)
void dwt2d_haar_kernel(const float* __restrict__ x, float* __restrict__ out) {
    const uint32_t tid = blockIdx.x * 256u + threadIdx.x;     // < 2^21
    const uint32_t j4 = tid & (QUADS_PER_ROW - 1);
    const uint32_t ip = (tid >> 8) & (ROWPAIRS - 1);          // output rows 2ip, 2ip+1
    const uint32_t b  = tid >> 17;

    // 32-bit element offsets (max 64M elems, fits easily)
    const uint32_t in_off = b * (uint32_t)(H_ * W_) + (4u * ip) * W_ + 8u * j4;
    const float4* p = reinterpret_cast<const float4*>(x + in_off);
    // rows stride 512 float4s = 8KB: all 8 loads as [p + imm]

    float4 r0a = __ldcs(p);
    float4 r0b = __ldcs(p + 1);
    float4 r1a = __ldcs(p + 512);
    float4 r1b = __ldcs(p + 513);
    float4 r2a = __ldcs(p + 1024);
    float4 r2b = __ldcs(p + 1025);
    float4 r3a = __ldcs(p + 1536);
    float4 r3b = __ldcs(p + 1537);

    const uint32_t o0 = b * (uint32_t)(HO * WO) + (2u * ip) * WO + 4u * j4;
    float* out0 = out + o0;                 // ll, rows o0 and o0+WO
    float* out1 = out0 + PLANE;             // lh
    float* out2 = out1 + PLANE;             // hl
    float* out3 = out2 + PLANE;             // hh

    #pragma unroll
    for (int s = 0; s < 4; s++) {
        float2 lo = haar2(r0a, r1a, s);
        float2 hi = haar2(r0b, r1b, s);
        float4 v; v.x = lo.x; v.y = lo.y; v.z = hi.x; v.w = hi.y;
        float* dst = (s == 0 ? out0 : s == 1 ? out1 : s == 2 ? out2 : out3);
        __stcs(reinterpret_cast<float4*>(dst), v);
    }
    #pragma unroll
    for (int s = 0; s < 4; s++) {
        float2 lo = haar2(r2a, r3a, s);
        float2 hi = haar2(r2b, r3b, s);
        float4 v; v.x = lo.x; v.y = lo.y; v.z = hi.x; v.w = hi.y;
        float* dst = (s == 0 ? out0 : s == 1 ? out1 : s == 2 ? out2 : out3);
        __stcs(reinterpret_cast<float4*>(dst + WO), v);
    }
}

extern "C" void kernel_launch(void* const* d_in, const int* in_sizes, int n_in,
                              void* d_out, int out_size) {
    const float* x = (const float*)d_in[0];
    float* out = (float*)d_out;

    const int64_t total = (int64_t)B_ * ROWPAIRS * QUADS_PER_ROW;  // 2,097,152
    const int threads = 256;
    const int blocks = (int)(total / threads);                     // 8192
    dwt2d_haar_kernel<<<blocks, threads>>>(x, out);
}

// round 5
// speedup vs baseline: 1.0062x; 1.0062x over previous
#include <cuda_runtime.h>
#include <cstdint>

// Haar DWT2D, software-pipelined: each thread processes 4 tiles (2x4 output
// pixels each), prefetching tile t+1's 8 loads before computing/storing tile t.
// Keeps ~8 loads in flight per thread continuously (no load-queue drain gaps).
//
// Input:  x  (16, 1, 2048, 2048) fp32
// Output: [ll | lh | hl | hh], each (16,1,1024,1024) fp32, concatenated.

#define B_  16
#define H_  2048
#define W_  2048
#define HO  (H_/2)            // 1024
#define WO  (W_/2)            // 1024
#define QUADS_PER_ROW (WO/4)  // 256
#define ROWPAIRS (HO/2)       // 512
#define PLANE (16u * 1024u * 1024u)
#define TILES_TOTAL (16u * 512u * 256u)   // 2,097,152
#define TILES_PER_THREAD 4
#define STRIDE_ (TILES_TOTAL / TILES_PER_THREAD)  // 524,288

__device__ __forceinline__ float safef(float v) {
    return isfinite(v) ? v : 0.0f;
}

struct Tile { float4 r[8]; };

__device__ __forceinline__ void load_tile(const float* __restrict__ x,
                                          uint32_t idx, Tile& T) {
    const uint32_t j4 = idx & (QUADS_PER_ROW - 1);
    const uint32_t ip = (idx >> 8) & (ROWPAIRS - 1);
    const uint32_t b  = idx >> 17;
    const uint32_t off = b * (uint32_t)(H_ * W_) + (4u * ip) * W_ + 8u * j4;
    const float4* p = reinterpret_cast<const float4*>(x + off);
    T.r[0] = __ldcs(p);
    T.r[1] = __ldcs(p + 1);
    T.r[2] = __ldcs(p + 512);
    T.r[3] = __ldcs(p + 513);
    T.r[4] = __ldcs(p + 1024);
    T.r[5] = __ldcs(p + 1025);
    T.r[6] = __ldcs(p + 1536);
    T.r[7] = __ldcs(p + 1537);
}

// top=(a0,b0,a1,b1), bot=(c0,d0,c1,d1): two adjacent 2x2 blocks -> subband s pair
__device__ __forceinline__ float2 haar2(float4 top, float4 bot, int s) {
    float a0 = safef(top.x), b0 = safef(top.y), a1 = safef(top.z), b1 = safef(top.w);
    float c0 = safef(bot.x), d0 = safef(bot.y), c1 = safef(bot.z), d1 = safef(bot.w);
    float p0 = a0 + c0, q0 = b0 + d0, r0 = c0 - a0, t0 = d0 - b0;
    float p1 = a1 + c1, q1 = b1 + d1, r1 = c1 - a1, t1 = d1 - b1;
    float2 v;
    switch (s) {
        case 0:  v.x = 0.5f * (p0 + q0); v.y = 0.5f * (p1 + q1); break;
        case 1:  v.x = 0.5f * (q0 - p0); v.y = 0.5f * (q1 - p1); break;
        case 2:  v.x = 0.5f * (r0 + t0); v.y = 0.5f * (r1 + t1); break;
        default: v.x = 0.5f * (t0 - r0); v.y = 0.5f * (t1 - r1); break;
    }
    return v;
}

__device__ __forceinline__ void store_tile(float* __restrict__ out,
                                           uint32_t idx, const Tile& T) {
    const uint32_t j4 = idx & (QUADS_PER_ROW - 1);
    const uint32_t ip = (idx >> 8) & (ROWPAIRS - 1);
    const uint32_t b  = idx >> 17;
    const uint32_t o0 = b * (uint32_t)(HO * WO) + (2u * ip) * WO + 4u * j4;
    float* base = out + o0;

    #pragma unroll
    for (int s = 0; s < 4; s++) {
        float2 lo = haar2(T.r[0], T.r[2], s);
        float2 hi = haar2(T.r[1], T.r[3], s);
        float4 v; v.x = lo.x; v.y = lo.y; v.z = hi.x; v.w = hi.y;
        __stcs(reinterpret_cast<float4*>(base + (uint32_t)s * PLANE), v);
    }
    #pragma unroll
    for (int s = 0; s < 4; s++) {
        float2 lo = haar2(T.r[4], T.r[6], s);
        float2 hi = haar2(T.r[5], T.r[7], s);
        float4 v; v.x = lo.x; v.y = lo.y; v.z = hi.x; v.w = hi.y;
        __stcs(reinterpret_cast<float4*>(base + (uint32_t)s * PLANE + WO), v);
    }
}

__global__ __launch_bounds__(256)
void dwt2d_haar_kernel(const float* __restrict__ x, float* __restrict__ out) {
    const uint32_t tid = blockIdx.x * 256u + threadIdx.x;   // < 2^19

    Tile A, B;
    load_tile(x, tid, A);

    #pragma unroll
    for (int t = 0; t < TILES_PER_THREAD; t++) {
        const uint32_t idx = tid + (uint32_t)t * STRIDE_;
        if (t + 1 < TILES_PER_THREAD) {
            load_tile(x, idx + STRIDE_, B);   // prefetch next tile first
        }
        store_tile(out, idx, A);              // then compute+store current
        A = B;
    }
}

extern "C" void kernel_launch(void* const* d_in, const int* in_sizes, int n_in,
                              void* d_out, int out_size) {
    const float* x = (const float*)d_in[0];
    float* out = (float*)d_out;

    const int threads = 256;
    const int blocks = (int)(STRIDE_ / threads);   // 2048 CTAs
    dwt2d_haar_kernel<<<blocks, threads>>>(x, out);
}